// round 15
// baseline (speedup 1.0000x reference)
#include <cuda_runtime.h>

#define N_PTS   8192
#define C_DIM   64
#define C4      (C_DIM/4)
#define NQ      (3*N_PTS)                 // 24576 queries
#define VOFF    ((size_t)4*N_PTS*C_DIM)   // float offset of out_coords

#define G       64
#define NCELL   (G*G)                     // 4096 cells
#define HC      0.015625f                 // 1/64, exact in fp32
#define CAP     8                         // bucket capacity per cell

#define TPB      256
#define BIN_CTAS 32
#define QPC      16                       // queries per CTA (2 per warp)
#define QW_CTAS  (NQ/QPC)                 // 1536 CTAs
#define NITEM    (N_PTS*C4 + N_PTS)       // 139264 copy items
#define ITEMS    91                       // ceil(NITEM / QW_CTAS)
#define FULL     0xffffffffu

typedef unsigned long long u64;
typedef unsigned int       u32;

// Bucketed grid, sentinel-padded (rebuilt every launch; replay-deterministic).
__device__ int    g_bcnt[NCELL];
__device__ float4 g_pts[NCELL * CAP];     // (x, y, |c|^2, idx bits); empty
                                          // slots hold (0,0,+inf,~0) sentinels
__device__ int    g_ovfcnt;
__device__ float4 g_ovf[N_PTS];           // overflow (normally ~0-3 entries)

// Grid-barrier counters (reset each use; replay-safe).
__device__ volatile int g_arr;
__device__ int          g_dep;

__device__ __forceinline__ int clamp_cell(float v) {
    int c = (int)floorf(v * 64.0f);
    return min(max(c, 0), G - 1);
}

// ---------------------------------------------------------------------------
// K_bin: sentinel-fill + zero counters -> barrier -> bucket scatter.
// 32 CTAs x 256 threads, one point each. Intra-cell order nondeterministic;
// downstream reduction is a set-min -> deterministic output.
// ---------------------------------------------------------------------------
__global__ void __launch_bounds__(TPB)
k_bin(const float2* __restrict__ c2)
{
    const int gi = blockIdx.x * TPB + threadIdx.x;   // 0..8191

    // phase 0: fill all 32768 slots with sentinels (d evaluates to +inf)
    const float4 snt = make_float4(0.0f, 0.0f,
                                   __int_as_float(0x7f800000),
                                   __int_as_float(-1));
    #pragma unroll
    for (int k = 0; k < 4; k++)
        g_pts[gi + k * (NCELL * CAP / 4)] = snt;
    if (gi < NCELL) g_bcnt[gi] = 0;
    if (gi == NCELL) g_ovfcnt = 0;

    // grid barrier over 32 trivially co-resident CTAs (replay-safe reset)
    __syncthreads();
    if (threadIdx.x == 0) {
        __threadfence();
        atomicAdd((int*)&g_arr, 1);
        while (g_arr != BIN_CTAS) __nanosleep(32);
        int p = atomicAdd(&g_dep, 1);
        if (p == BIN_CTAS - 1) {
            g_dep = 0;
            __threadfence();
            *(int*)&g_arr = 0;
        }
    }
    __syncthreads();

    // phase 1: scatter
    float2 c = __ldg(&c2[gi]);
    const int cell = clamp_cell(c.y) * G + clamp_cell(c.x);
    float sc = __fadd_rn(__fmul_rn(c.x, c.x), __fmul_rn(c.y, c.y));
    float4 p = make_float4(c.x, c.y, sc, __int_as_float(gi));

    int pos = atomicAdd(&g_bcnt[cell], 1);
    if (pos < CAP) g_pts[cell * CAP + pos] = p;
    else           g_ovf[atomicAdd(&g_ovfcnt, 1)] = p;   // capacity N_PTS: safe
}

// ---------------------------------------------------------------------------
// Warp-collective exact NN for one query: flat sentinel-padded slot sweep.
// Exact per-pair semantics (verified bit-identical to reference):
//   m = fma(a1, py, RN(a0*px));  d = fma(m, -2, RN(sa+sc))
// Lexicographic (ordered-d, idx) min == jnp.argmin first occurrence.
// ---------------------------------------------------------------------------
__device__ __forceinline__ int warp_nn(float a0, float a1, float sa, int lane)
{
    const float sa_ = sa;
    const int cx = clamp_cell(a0);
    const int cy = clamp_cell(a1);

    // query clearance to the point domain [0,1] per axis
    const float dxo = fmaxf(fmaxf(a0 - 1.0f, -a0), 0.0f);
    const float dyo = fmaxf(fmaxf(a1 - 1.0f, -a1), 0.0f);
    const float dxo2 = dxo * dxo;
    const float dyo2 = dyo * dyo;

    u64 bestk = ~0ull;

    #define EVAL_PT(P) do {                                                  \
        float m_ = __fmaf_rn(a1, (P).y, __fmul_rn(a0, (P).x));               \
        float d_ = __fmaf_rn(m_, -2.0f, __fadd_rn(sa_, (P).z));              \
        u32 ub_ = __float_as_uint(d_);                                       \
        ub_ = (ub_ & 0x80000000u) ? ~ub_ : (ub_ | 0x80000000u);              \
        u64 key_ = ((u64)ub_ << 32) | (u32)__float_as_uint((P).w);           \
        bestk = (key_ < bestk) ? key_ : bestk;                               \
    } while (0)

    // overflow points first (normally none) — superset scan is min-safe
    const int ovn = __ldg(&g_ovfcnt);
    for (int t = lane; t < ovn; t += 32) {
        float4 p = __ldg(&g_ovf[t]);
        EVAL_PT(p);
    }

    int r = 1;
    while (true) {
        const int x0 = max(cx - r, 0), x1 = min(cx + r, G - 1);
        const int y0 = max(cy - r, 0), y1 = min(cy + r, G - 1);
        const int w = x1 - x0 + 1;
        const int rowlen = w * CAP;                       // slots per row
        const int nslots = (y1 - y0 + 1) * rowlen;
        // exact magic division by rowlen for sl < 32768 (proof in notes)
        const u32 mgc = (u32)(0x100000000ull / (u32)rowlen) + 1u;
        const int rowbase = (y0 * G + x0) * CAP;

        for (int base = 0; base < nslots; base += 32) {
            const int sl = base + lane;
            if (sl < nslots) {
                int yy  = (int)(((u64)(u32)sl * mgc) >> 32);
                int rem = sl - yy * rowlen;
                float4 p = __ldg(&g_pts[rowbase + yy * (G * CAP) + rem]);
                EVAL_PT(p);                 // sentinels eval to +inf: harmless
            }
        }

        // lb^2 to the unscanned region: per side-slab, (axis gap)^2 +
        // (query clearance to [0,1] in the other axis)^2.
        float lb2 = __int_as_float(0x7f800000);
        if (x0 > 0) {
            float dx = fmaxf(__fsub_rn(a0, (float)x0 * HC), 0.0f);
            lb2 = fminf(lb2, __fmaf_rn(dx, dx, dyo2));
        }
        if (x1 < G - 1) {
            float dx = fmaxf(__fsub_rn((float)(x1 + 1) * HC, a0), 0.0f);
            lb2 = fminf(lb2, __fmaf_rn(dx, dx, dyo2));
        }
        if (y0 > 0) {
            float dy = fmaxf(__fsub_rn(a1, (float)y0 * HC), 0.0f);
            lb2 = fminf(lb2, __fmaf_rn(dy, dy, dxo2));
        }
        if (y1 < G - 1) {
            float dy = fmaxf(__fsub_rn((float)(y1 + 1) * HC, a1), 0.0f);
            lb2 = fminf(lb2, __fmaf_rn(dy, dy, dxo2));
        }

        if (lb2 > 1e18f) break;                 // whole grid scanned

        // warp-wide best-so-far distance (sentinel/empty decode -> +inf)
        u32 mu = __reduce_min_sync(FULL, (u32)(bestk >> 32));
        float bd;
        if (mu == 0xffffffffu)      bd = __int_as_float(0x7f800000);
        else if (mu & 0x80000000u)  bd = __uint_as_float(mu & 0x7fffffffu);
        else                        bd = __uint_as_float(~mu);
        if (lb2 > bd + 1e-4f) break;            // margin >> fp slack (~4e-6)
        r = 2 * r + 1;
    }
    #undef EVAL_PT

    // final lexicographic (d, idx) warp reduction
    u32 bub = (u32)(bestk >> 32);
    u32 mu  = __reduce_min_sync(FULL, bub);
    u32 cnd = (bub == mu) ? (u32)bestk : 0xffffffffu;
    return (int)__reduce_min_sync(FULL, cnd);
}

// ---------------------------------------------------------------------------
// K_query: 16 queries per CTA (2 per warp) + distributed output copies +
// coalesced value-row gather (exactly 1 float4 per thread).
// ---------------------------------------------------------------------------
__global__ void __launch_bounds__(TPB)
k_query(const float2* __restrict__ c2,
        const float*  __restrict__ spacing,
        const float*  __restrict__ shift,
        const float4* __restrict__ val4,
        float*        __restrict__ out)
{
    __shared__ int widx[QPC];
    const int lane = threadIdx.x & 31;
    const int wid  = threadIdx.x >> 5;

    float s0  = __ldg(&spacing[0]), s1  = __ldg(&spacing[1]);
    float sh0 = __ldg(&shift[0]),   sh1 = __ldg(&shift[1]);

    // ---- distributed output copies (independent of binning results) ----
    if (threadIdx.x < ITEMS) {
        int item = blockIdx.x * ITEMS + threadIdx.x;
        if (item < N_PTS * C4) {
            reinterpret_cast<float4*>(out)[item] = __ldg(&val4[item]);
        } else if (item < NITEM) {
            int i = item - N_PTS * C4;
            float2 cc = __ldg(&c2[i]);
            float xs = __fadd_rn(cc.x, s0);
            float ys = __fadd_rn(cc.y, s1);
            float2* outc = reinterpret_cast<float2*>(out + VOFF);
            outc[i]             = cc;
            outc[N_PTS   + i]   = make_float2(xs,   ys);
            outc[2*N_PTS + i]   = make_float2(cc.x, ys);
            outc[3*N_PTS + i]   = make_float2(xs,   cc.y);
        }
    }

    // ---- 2 queries per warp, sequential ----
    #pragma unroll
    for (int k = 0; k < 2; k++) {
        const int q = blockIdx.x * QPC + wid * 2 + k;   // 0..24575
        const int g = q >> 13;
        const int i = q & (N_PTS - 1);

        float2 c = __ldg(&c2[i]);
        float nc0, nc1;
        if (g == 0)      { nc0 = __fadd_rn(c.x, s0); nc1 = __fadd_rn(c.y, s1); }
        else if (g == 1) { nc0 = c.x;                nc1 = __fadd_rn(c.y, s1); }
        else             { nc0 = __fadd_rn(c.x, s0); nc1 = c.y;                }

        const float a0 = __fsub_rn(nc0, sh0);
        const float a1 = __fsub_rn(nc1, sh1);
        const float sa = __fadd_rn(__fmul_rn(a0, a0), __fmul_rn(a1, a1));

        int win = warp_nn(a0, a1, sa, lane);
        if (lane == 0) widx[wid * 2 + k] = win;
    }
    __syncthreads();

    // ---- coalesced gather: 16 winner rows, 1 float4 per thread ----
    {
        int rr  = threadIdx.x >> 4;         // 0..15
        int ccx = threadIdx.x & (C4 - 1);   // 0..15
        int row = blockIdx.x * QPC + rr;
        reinterpret_cast<float4*>(out)[(size_t)(N_PTS + row) * C4 + ccx] =
            __ldg(&val4[(size_t)widx[rr] * C4 + ccx]);
    }
}

// ---------------------------------------------------------------------------
extern "C" void kernel_launch(void* const* d_in, const int* in_sizes, int n_in,
                              void* d_out, int out_size)
{
    const float4* val4    = (const float4*)d_in[0];
    const float2* c2      = (const float2*)d_in[1];
    const float*  spacing = (const float*) d_in[2];
    const float*  shift   = (const float*) d_in[3];
    float* out = (float*)d_out;

    k_bin<<<BIN_CTAS, TPB>>>(c2);
    k_query<<<QW_CTAS, TPB>>>(c2, spacing, shift, val4, out);
}